// round 2
// baseline (speedup 1.0000x reference)
#include <cuda_runtime.h>

#define NN 100000
#define EE 1600000
#define FF 64
#define CC 10
#define LL 4
#define BB 128

// scratch (allocation-free rule: __device__ globals)
__device__ float d_h[(size_t)NN * FF];
__device__ float d_agg[(size_t)NN * FF];
__device__ int d_src[EE];
__device__ int d_dst[EE];
__device__ int d_batch[NN];
__device__ int d_flags[2];   // [0]: edges are int32, [1]: batch is int32

// ---------------------------------------------------------------------------
// dtype detection: int64 nonneg values < 2^31 have zero upper words.
// ---------------------------------------------------------------------------
__global__ void detect_kernel(const unsigned* __restrict__ ei,
                              const unsigned* __restrict__ bt,
                              int* __restrict__ flags) {
    if (threadIdx.x == 0) { flags[0] = 0; flags[1] = 0; }
    __syncthreads();
    int t = threadIdx.x;  // 256 threads
    // edges: sample entry e = t*6000 (< EE); upper word if int64 at [2e+1]
    unsigned a = ei[2 * (t * 6000) + 1];
    if (a != 0u) atomicOr(&flags[0], 1);
    // batch: sample i in [25000, 50000) so 2i+1 < NN stays in-bounds for int32
    int i = NN / 4 + t * 97;
    unsigned b = bt[2 * i + 1];
    if (b != 0u) atomicOr(&flags[1], 1);
}

__global__ void cvt_edges(const void* __restrict__ ei,
                          int* __restrict__ src, int* __restrict__ dst,
                          const int* __restrict__ flags) {
    int e = blockIdx.x * blockDim.x + threadIdx.x;
    if (e >= EE) return;
    if (flags[0]) {  // int32 payload
        src[e] = ((const int*)ei)[e];
        dst[e] = ((const int*)ei)[EE + e];
    } else {         // int64 payload
        src[e] = (int)((const long long*)ei)[e];
        dst[e] = (int)((const long long*)ei)[EE + e];
    }
}

__global__ void cvt_batch(const void* __restrict__ bt,
                          int* __restrict__ out, const int* __restrict__ flags) {
    int i = blockIdx.x * blockDim.x + threadIdx.x;
    if (i >= NN) return;
    out[i] = flags[1] ? ((const int*)bt)[i] : (int)((const long long*)bt)[i];
}

// ---------------------------------------------------------------------------
// agg = src (float4 copy), used once to init agg = x for layer 0
// ---------------------------------------------------------------------------
__global__ void copy_kernel(const float* __restrict__ src, float* __restrict__ dst, int n4) {
    int i = blockIdx.x * blockDim.x + threadIdx.x;
    if (i < n4) ((float4*)dst)[i] = ((const float4*)src)[i];
}

// ---------------------------------------------------------------------------
// agg[dst[e]] += hin[src[e]]  — thread per (edge, 4-feature chunk)
// ---------------------------------------------------------------------------
__global__ void edge_kernel(const float* __restrict__ hin, float* __restrict__ agg,
                            const int* __restrict__ src,
                            const int* __restrict__ dst) {
    int t = blockIdx.x * blockDim.x + threadIdx.x;
    if (t >= EE * 16) return;
    int e = t >> 4;
    int c = t & 15;
    int s = src[e];
    int d = dst[e];
    if ((unsigned)s >= NN || (unsigned)d >= NN) return;  // safety
    float4 v = ((const float4*)(hin + (size_t)s * FF))[c];
    float* a = agg + (size_t)d * FF + c * 4;
    atomicAdd(a + 0, v.x);
    atomicAdd(a + 1, v.y);
    atomicAdd(a + 2, v.z);
    atomicAdd(a + 3, v.w);
}

// ---------------------------------------------------------------------------
// out = sigmoid(sigmoid(in @ W1) @ W2); also writes out2 (next layer's agg init)
// warp-per-row, W1/W2 in smem, row broadcast via shfl
// ---------------------------------------------------------------------------
__device__ __forceinline__ float fast_sigmoid(float x) {
    return __fdividef(1.0f, 1.0f + __expf(-x));
}

__global__ void mlp_kernel(const float* __restrict__ in, float* __restrict__ out,
                           float* __restrict__ out2,
                           const float* __restrict__ W1, const float* __restrict__ W2) {
    __shared__ float w1[FF * FF];
    __shared__ float w2[FF * FF];
    for (int i = threadIdx.x; i < FF * FF; i += blockDim.x) {
        w1[i] = W1[i];
        w2[i] = W2[i];
    }
    __syncthreads();

    int lane = threadIdx.x & 31;
    int warp = (blockIdx.x * blockDim.x + threadIdx.x) >> 5;
    int nw = (gridDim.x * blockDim.x) >> 5;

    for (int r = warp; r < NN; r += nw) {
        const float* row = in + (size_t)r * FF;
        float x0 = row[lane];
        float x1 = row[lane + 32];
        float a0 = 0.f, a1 = 0.f;
#pragma unroll
        for (int k = 0; k < 32; k++) {
            float xk = __shfl_sync(0xffffffffu, x0, k);
            a0 = fmaf(xk, w1[k * FF + lane], a0);
            a1 = fmaf(xk, w1[k * FF + lane + 32], a1);
        }
#pragma unroll
        for (int k = 0; k < 32; k++) {
            float xk = __shfl_sync(0xffffffffu, x1, k);
            a0 = fmaf(xk, w1[(k + 32) * FF + lane], a0);
            a1 = fmaf(xk, w1[(k + 32) * FF + lane + 32], a1);
        }
        float y0 = fast_sigmoid(a0);
        float y1 = fast_sigmoid(a1);

        a0 = 0.f; a1 = 0.f;
#pragma unroll
        for (int k = 0; k < 32; k++) {
            float yk = __shfl_sync(0xffffffffu, y0, k);
            a0 = fmaf(yk, w2[k * FF + lane], a0);
            a1 = fmaf(yk, w2[k * FF + lane + 32], a1);
        }
#pragma unroll
        for (int k = 0; k < 32; k++) {
            float yk = __shfl_sync(0xffffffffu, y1, k);
            a0 = fmaf(yk, w2[(k + 32) * FF + lane], a0);
            a1 = fmaf(yk, w2[(k + 32) * FF + lane + 32], a1);
        }
        float z0 = fast_sigmoid(a0);
        float z1 = fast_sigmoid(a1);

        size_t o = (size_t)r * FF;
        out[o + lane] = z0;
        out[o + lane + 32] = z1;
        out2[o + lane] = z0;       // pre-init next layer's agg = h
        out2[o + lane + 32] = z1;
    }
}

// ---------------------------------------------------------------------------
// xr[batch[i]] += h[i]  (xr zeroed beforehand by memset of d_out)
// ---------------------------------------------------------------------------
__global__ void pool_kernel(const float* __restrict__ h,
                            const int* __restrict__ batch,
                            float* __restrict__ xr) {
    int t = blockIdx.x * blockDim.x + threadIdx.x;
    if (t < NN * FF) {
        int i = t >> 6;
        int f = t & 63;
        int b = batch[i];
        if ((unsigned)b < BB) atomicAdd(&xr[b * FF + f], h[t]);
    }
}

// ---------------------------------------------------------------------------
// logits = xr @ fc_w^T + fc_b; out = log_softmax(logits)
// ---------------------------------------------------------------------------
__global__ void head_kernel(const float* __restrict__ xr, const float* __restrict__ fcw,
                            const float* __restrict__ fcb, float* __restrict__ out) {
    __shared__ float w[CC * FF];
    __shared__ float b[CC];
    for (int i = threadIdx.x; i < CC * FF; i += blockDim.x) w[i] = fcw[i];
    if (threadIdx.x < CC) b[threadIdx.x] = fcb[threadIdx.x];
    __syncthreads();

    int r = threadIdx.x;
    if (r < BB) {
        float lg[CC];
        float m = -1e30f;
        const float* row = xr + r * FF;
#pragma unroll
        for (int j = 0; j < CC; j++) {
            float a = b[j];
#pragma unroll
            for (int k = 0; k < FF; k++) a = fmaf(row[k], w[j * FF + k], a);
            lg[j] = a;
            m = fmaxf(m, a);
        }
        float s = 0.f;
#pragma unroll
        for (int j = 0; j < CC; j++) s += expf(lg[j] - m);
        float lse = m + logf(s);
#pragma unroll
        for (int j = 0; j < CC; j++) out[r * CC + j] = lg[j] - lse;
    }
}

// ---------------------------------------------------------------------------
extern "C" void kernel_launch(void* const* d_in, const int* in_sizes, int n_in,
                              void* d_out, int out_size) {
    const float* x = (const float*)d_in[0];
    const void* ei = d_in[1];        // [2, E] int32 or int64
    const void* batch = d_in[2];     // [N] int32 or int64
    const float* W1s = (const float*)d_in[3];             // [L, F, F]
    const float* W2s = (const float*)d_in[4];             // [L, F, F]
    const float* fcw = (const float*)d_in[5];             // [C, F]
    const float* fcb = (const float*)d_in[6];             // [C]
    float* out = (float*)d_out;      // [B*C] logsoftmax ++ [B*F] xr

    float *h, *agg;
    int *src, *dst, *bt, *flags;
    cudaGetSymbolAddress((void**)&h, d_h);
    cudaGetSymbolAddress((void**)&agg, d_agg);
    cudaGetSymbolAddress((void**)&src, d_src);
    cudaGetSymbolAddress((void**)&dst, d_dst);
    cudaGetSymbolAddress((void**)&bt, d_batch);
    cudaGetSymbolAddress((void**)&flags, d_flags);

    // dtype detect + convert indices to packed int32
    detect_kernel<<<1, 256>>>((const unsigned*)ei, (const unsigned*)batch, flags);
    cvt_edges<<<(EE + 255) / 256, 256>>>(ei, src, dst, flags);
    cvt_batch<<<(NN + 255) / 256, 256>>>(batch, bt, flags);

    // zero output (xr region needs zero for atomics; logits fully overwritten)
    cudaMemsetAsync(d_out, 0, (size_t)out_size * sizeof(float));

    // layer 0: agg = x (later layers: MLP dual-writes agg = h)
    copy_kernel<<<(NN * FF / 4 + 255) / 256, 256>>>(x, agg, NN * FF / 4);

    const float* hin = x;
    for (int l = 0; l < LL; l++) {
        edge_kernel<<<(EE * 16 + 255) / 256, 256>>>(hin, agg, src, dst);
        mlp_kernel<<<592, 256>>>(agg, h, agg, W1s + l * FF * FF, W2s + l * FF * FF);
        hin = h;
    }

    pool_kernel<<<(NN * FF + 255) / 256, 256>>>(h, bt, out + BB * CC);
    head_kernel<<<1, 128>>>(out + BB * CC, fcw, fcb, out);
}

// round 3
// speedup vs baseline: 1.8107x; 1.8107x over previous
#include <cuda_runtime.h>

#define NN 100000
#define EE 1600000
#define FF 64
#define CC 10
#define LL 4
#define BB 128

// ---- scratch (__device__ globals; no allocs allowed) ----------------------
__device__ float d_hA[(size_t)NN * FF];
__device__ float d_hB[(size_t)NN * FF];
__device__ int d_src[EE];
__device__ int d_dst[EE];
__device__ int d_nbr[EE];           // src sorted by dst (CSR adjacency)
__device__ int d_deg[NN];
__device__ int d_rowptr[NN + 1];
__device__ int d_cursor[NN];
__device__ int d_batch[NN];
__device__ int d_bsum[1024];        // per-block degree sums for scan
__device__ int d_boff[1024];
__device__ int d_flags[2];

#define NB 782                      // ceil(NN/128)

// ---------------------------------------------------------------------------
// dtype detection: int64 nonneg values < 2^31 have zero upper words.
// ---------------------------------------------------------------------------
__global__ void detect_kernel(const unsigned* __restrict__ ei,
                              const unsigned* __restrict__ bt,
                              int* __restrict__ flags) {
    if (threadIdx.x == 0) { flags[0] = 0; flags[1] = 0; }
    __syncthreads();
    int t = threadIdx.x;  // 256 threads
    unsigned a = ei[2 * (t * 6000) + 1];
    if (a != 0u) atomicOr(&flags[0], 1);
    int i = NN / 4 + t * 97;
    unsigned b = bt[2 * i + 1];
    if (b != 0u) atomicOr(&flags[1], 1);
}

// convert indices to int32 AND histogram degrees (deg pre-zeroed)
__global__ void cvt_edges(const void* __restrict__ ei,
                          int* __restrict__ src, int* __restrict__ dst,
                          int* __restrict__ deg, const int* __restrict__ flags) {
    int e = blockIdx.x * blockDim.x + threadIdx.x;
    if (e >= EE) return;
    int s, d;
    if (flags[0]) {
        s = ((const int*)ei)[e];
        d = ((const int*)ei)[EE + e];
    } else {
        s = (int)((const long long*)ei)[e];
        d = (int)((const long long*)ei)[EE + e];
    }
    src[e] = s;
    dst[e] = d;
    if ((unsigned)d < NN) atomicAdd(&deg[d], 1);
}

__global__ void cvt_batch(const void* __restrict__ bt,
                          int* __restrict__ out, const int* __restrict__ flags) {
    int i = blockIdx.x * blockDim.x + threadIdx.x;
    if (i >= NN) return;
    out[i] = flags[1] ? ((const int*)bt)[i] : (int)((const long long*)bt)[i];
}

// ---------------------------------------------------------------------------
// CSR build: block sums -> block-offset scan -> local scan -> scatter
// ---------------------------------------------------------------------------
__global__ void k_bsum(const int* __restrict__ deg, int* __restrict__ bsum) {
    __shared__ int sh[128];
    int i = blockIdx.x * 128 + threadIdx.x;
    int v = (i < NN) ? deg[i] : 0;
    sh[threadIdx.x] = v;
    __syncthreads();
    for (int s = 64; s > 0; s >>= 1) {
        if (threadIdx.x < s) sh[threadIdx.x] += sh[threadIdx.x + s];
        __syncthreads();
    }
    if (threadIdx.x == 0) bsum[blockIdx.x] = sh[0];
}

__global__ void k_bscan(const int* __restrict__ bsum, int* __restrict__ boff) {
    __shared__ int sh[1024];
    int t = threadIdx.x;
    int v = (t < NB) ? bsum[t] : 0;
    sh[t] = v;
    __syncthreads();
    for (int s = 1; s < 1024; s <<= 1) {
        int add = (t >= s) ? sh[t - s] : 0;
        __syncthreads();
        sh[t] += add;
        __syncthreads();
    }
    if (t < NB) boff[t] = sh[t] - v;  // exclusive
}

__global__ void k_rowptr(const int* __restrict__ deg, const int* __restrict__ boff,
                         int* __restrict__ rowptr, int* __restrict__ cursor) {
    __shared__ int sh[128];
    int i = blockIdx.x * 128 + threadIdx.x;
    int t = threadIdx.x;
    int v = (i < NN) ? deg[i] : 0;
    sh[t] = v;
    __syncthreads();
    for (int s = 1; s < 128; s <<= 1) {
        int add = (t >= s) ? sh[t - s] : 0;
        __syncthreads();
        sh[t] += add;
        __syncthreads();
    }
    if (i < NN) {
        int off = boff[blockIdx.x] + sh[t] - v;  // exclusive prefix
        rowptr[i] = off;
        cursor[i] = off;
    }
    if (blockIdx.x == 0 && t == 0) rowptr[NN] = EE;
}

__global__ void k_scatter(const int* __restrict__ src, const int* __restrict__ dst,
                          int* __restrict__ cursor, int* __restrict__ nbr) {
    int e = blockIdx.x * blockDim.x + threadIdx.x;
    if (e >= EE) return;
    int d = dst[e];
    if ((unsigned)d >= NN) return;
    int p = atomicAdd(&cursor[d], 1);
    nbr[p] = src[e];
}

// ---------------------------------------------------------------------------
// Fused GIN layer: hout = sig(sig((h + sum_nbr h) @ W1) @ W2)
// persistent blocks, warp-per-node, weights in smem, shfl-broadcast MLP
// ---------------------------------------------------------------------------
__device__ __forceinline__ float fast_sigmoid(float x) {
    return __fdividef(1.0f, 1.0f + __expf(-x));
}

__global__ void __launch_bounds__(256) layer_kernel(
    const float* __restrict__ hin, float* __restrict__ hout,
    const float* __restrict__ W1, const float* __restrict__ W2,
    const int* __restrict__ rowptr, const int* __restrict__ nbr) {
    __shared__ float w1[FF * FF];
    __shared__ float w2[FF * FF];
    for (int i = threadIdx.x; i < FF * FF; i += 256) {
        w1[i] = W1[i];
        w2[i] = W2[i];
    }
    __syncthreads();

    int lane = threadIdx.x & 31;
    int warp = (blockIdx.x * 256 + threadIdx.x) >> 5;
    int nw = (gridDim.x * 256) >> 5;

    for (int r = warp; r < NN; r += nw) {
        // aggregation: self + neighbors (gather via CSR)
        size_t rb = (size_t)r * FF;
        float a0 = hin[rb + lane];
        float a1 = hin[rb + lane + 32];
        int beg = rowptr[r], end = rowptr[r + 1];
        for (int j = beg; j < end; j++) {
            int s = __ldg(&nbr[j]);
            size_t sb = (size_t)s * FF;
            a0 += hin[sb + lane];
            a1 += hin[sb + lane + 32];
        }

        // MLP: two 64x64 linears, each + sigmoid
        float b0 = 0.f, b1 = 0.f;
#pragma unroll
        for (int k = 0; k < 32; k++) {
            float xk = __shfl_sync(0xffffffffu, a0, k);
            b0 = fmaf(xk, w1[k * FF + lane], b0);
            b1 = fmaf(xk, w1[k * FF + lane + 32], b1);
        }
#pragma unroll
        for (int k = 0; k < 32; k++) {
            float xk = __shfl_sync(0xffffffffu, a1, k);
            b0 = fmaf(xk, w1[(k + 32) * FF + lane], b0);
            b1 = fmaf(xk, w1[(k + 32) * FF + lane + 32], b1);
        }
        float y0 = fast_sigmoid(b0);
        float y1 = fast_sigmoid(b1);

        b0 = 0.f; b1 = 0.f;
#pragma unroll
        for (int k = 0; k < 32; k++) {
            float yk = __shfl_sync(0xffffffffu, y0, k);
            b0 = fmaf(yk, w2[k * FF + lane], b0);
            b1 = fmaf(yk, w2[k * FF + lane + 32], b1);
        }
#pragma unroll
        for (int k = 0; k < 32; k++) {
            float yk = __shfl_sync(0xffffffffu, y1, k);
            b0 = fmaf(yk, w2[(k + 32) * FF + lane], b0);
            b1 = fmaf(yk, w2[(k + 32) * FF + lane + 32], b1);
        }
        hout[rb + lane] = fast_sigmoid(b0);
        hout[rb + lane + 32] = fast_sigmoid(b1);
    }
}

// ---------------------------------------------------------------------------
// xr[batch[i]] += h[i]
// ---------------------------------------------------------------------------
__global__ void pool_kernel(const float* __restrict__ h,
                            const int* __restrict__ batch,
                            float* __restrict__ xr) {
    int t = blockIdx.x * blockDim.x + threadIdx.x;
    if (t < NN * FF) {
        int i = t >> 6;
        int f = t & 63;
        int b = batch[i];
        if ((unsigned)b < BB) atomicAdd(&xr[b * FF + f], h[t]);
    }
}

// ---------------------------------------------------------------------------
// logits = xr @ fc_w^T + fc_b; out = log_softmax(logits)
// ---------------------------------------------------------------------------
__global__ void head_kernel(const float* __restrict__ xr, const float* __restrict__ fcw,
                            const float* __restrict__ fcb, float* __restrict__ out) {
    __shared__ float w[CC * FF];
    __shared__ float b[CC];
    for (int i = threadIdx.x; i < CC * FF; i += blockDim.x) w[i] = fcw[i];
    if (threadIdx.x < CC) b[threadIdx.x] = fcb[threadIdx.x];
    __syncthreads();

    int r = threadIdx.x;
    if (r < BB) {
        float lg[CC];
        float m = -1e30f;
        const float* row = xr + r * FF;
#pragma unroll
        for (int j = 0; j < CC; j++) {
            float a = b[j];
#pragma unroll
            for (int k = 0; k < FF; k++) a = fmaf(row[k], w[j * FF + k], a);
            lg[j] = a;
            m = fmaxf(m, a);
        }
        float s = 0.f;
#pragma unroll
        for (int j = 0; j < CC; j++) s += expf(lg[j] - m);
        float lse = m + logf(s);
#pragma unroll
        for (int j = 0; j < CC; j++) out[r * CC + j] = lg[j] - lse;
    }
}

// ---------------------------------------------------------------------------
extern "C" void kernel_launch(void* const* d_in, const int* in_sizes, int n_in,
                              void* d_out, int out_size) {
    const float* x = (const float*)d_in[0];
    const void* ei = d_in[1];
    const void* batch = d_in[2];
    const float* W1s = (const float*)d_in[3];
    const float* W2s = (const float*)d_in[4];
    const float* fcw = (const float*)d_in[5];
    const float* fcb = (const float*)d_in[6];
    float* out = (float*)d_out;

    float *hA, *hB;
    int *src, *dst, *nbr, *deg, *rowptr, *cursor, *bt, *bsum, *boff, *flags;
    cudaGetSymbolAddress((void**)&hA, d_hA);
    cudaGetSymbolAddress((void**)&hB, d_hB);
    cudaGetSymbolAddress((void**)&src, d_src);
    cudaGetSymbolAddress((void**)&dst, d_dst);
    cudaGetSymbolAddress((void**)&nbr, d_nbr);
    cudaGetSymbolAddress((void**)&deg, d_deg);
    cudaGetSymbolAddress((void**)&rowptr, d_rowptr);
    cudaGetSymbolAddress((void**)&cursor, d_cursor);
    cudaGetSymbolAddress((void**)&bt, d_batch);
    cudaGetSymbolAddress((void**)&bsum, d_bsum);
    cudaGetSymbolAddress((void**)&boff, d_boff);
    cudaGetSymbolAddress((void**)&flags, d_flags);

    // indices -> int32, degree histogram, CSR build
    cudaMemsetAsync(deg, 0, NN * sizeof(int));
    detect_kernel<<<1, 256>>>((const unsigned*)ei, (const unsigned*)batch, flags);
    cvt_edges<<<(EE + 255) / 256, 256>>>(ei, src, dst, deg, flags);
    cvt_batch<<<(NN + 255) / 256, 256>>>(batch, bt, flags);
    k_bsum<<<NB, 128>>>(deg, bsum);
    k_bscan<<<1, 1024>>>(bsum, boff);
    k_rowptr<<<NB, 128>>>(deg, boff, rowptr, cursor);
    k_scatter<<<(EE + 255) / 256, 256>>>(src, dst, cursor, nbr);

    // zero output (xr region needs zeros for pool atomics)
    cudaMemsetAsync(d_out, 0, (size_t)out_size * sizeof(float));

    // 4 fused GIN layers, ping-pong h buffers
    const int grid = 148 * 7;  // 32KB smem/block -> 7 blocks/SM
    layer_kernel<<<grid, 256>>>(x,  hA, W1s + 0 * FF * FF, W2s + 0 * FF * FF, rowptr, nbr);
    layer_kernel<<<grid, 256>>>(hA, hB, W1s + 1 * FF * FF, W2s + 1 * FF * FF, rowptr, nbr);
    layer_kernel<<<grid, 256>>>(hB, hA, W1s + 2 * FF * FF, W2s + 2 * FF * FF, rowptr, nbr);
    layer_kernel<<<grid, 256>>>(hA, hB, W1s + 3 * FF * FF, W2s + 3 * FF * FF, rowptr, nbr);

    pool_kernel<<<(NN * FF + 255) / 256, 256>>>(hB, bt, out + BB * CC);
    head_kernel<<<1, 128>>>(out + BB * CC, fcw, fcb, out);
}

// round 6
// speedup vs baseline: 2.0795x; 1.1485x over previous
#include <cuda_runtime.h>
#include <mma.h>
#include <cstdint>

using namespace nvcuda;

#define NN 100000
#define EE 1600000
#define FF 64
#define CC 10
#define LL 4
#define BB 128
#define NB 782                      // ceil(NN/128)
#define NTILE 782                   // row tiles of 128 for the MLP GEMM
#define LDA 72                      // smem leading dim (pad 64 -> 72 floats)

// ---- scratch (__device__ globals; no allocs allowed) ----------------------
__device__ float d_hA[(size_t)NN * FF];   // agg scratch
__device__ float d_hB[(size_t)NN * FF];   // h ping buffer
__device__ int d_src[EE];
__device__ int d_dst[EE];
__device__ int d_nbr[EE];
__device__ int d_deg[NN];
__device__ int d_rowptr[NN + 1];
__device__ int d_cursor[NN];
__device__ int d_batch[NN];
__device__ int d_bsum[1024];
__device__ int d_boff[1024];
__device__ int d_flags[2];

// ============================================================================
// preprocessing (dtype detect, int32 convert, CSR build)
// ============================================================================
__global__ void detect_kernel(const unsigned* __restrict__ ei,
                              const unsigned* __restrict__ bt,
                              int* __restrict__ flags) {
    if (threadIdx.x == 0) { flags[0] = 0; flags[1] = 0; }
    __syncthreads();
    int t = threadIdx.x;
    unsigned a = ei[2 * (t * 6000) + 1];
    if (a != 0u) atomicOr(&flags[0], 1);
    int i = NN / 4 + t * 97;
    unsigned b = bt[2 * i + 1];
    if (b != 0u) atomicOr(&flags[1], 1);
}

__global__ void cvt_edges(const void* __restrict__ ei,
                          int* __restrict__ src, int* __restrict__ dst,
                          int* __restrict__ deg, const int* __restrict__ flags) {
    int e = blockIdx.x * blockDim.x + threadIdx.x;
    if (e >= EE) return;
    int s, d;
    if (flags[0]) {
        s = ((const int*)ei)[e];
        d = ((const int*)ei)[EE + e];
    } else {
        s = (int)((const long long*)ei)[e];
        d = (int)((const long long*)ei)[EE + e];
    }
    src[e] = s;
    dst[e] = d;
    if ((unsigned)d < NN) atomicAdd(&deg[d], 1);
}

__global__ void cvt_batch(const void* __restrict__ bt,
                          int* __restrict__ out, const int* __restrict__ flags) {
    int i = blockIdx.x * blockDim.x + threadIdx.x;
    if (i >= NN) return;
    out[i] = flags[1] ? ((const int*)bt)[i] : (int)((const long long*)bt)[i];
}

__global__ void k_bsum(const int* __restrict__ deg, int* __restrict__ bsum) {
    __shared__ int sh[128];
    int i = blockIdx.x * 128 + threadIdx.x;
    int v = (i < NN) ? deg[i] : 0;
    sh[threadIdx.x] = v;
    __syncthreads();
    for (int s = 64; s > 0; s >>= 1) {
        if (threadIdx.x < s) sh[threadIdx.x] += sh[threadIdx.x + s];
        __syncthreads();
    }
    if (threadIdx.x == 0) bsum[blockIdx.x] = sh[0];
}

__global__ void k_bscan(const int* __restrict__ bsum, int* __restrict__ boff) {
    __shared__ int sh[1024];
    int t = threadIdx.x;
    int v = (t < NB) ? bsum[t] : 0;
    sh[t] = v;
    __syncthreads();
    for (int s = 1; s < 1024; s <<= 1) {
        int add = (t >= s) ? sh[t - s] : 0;
        __syncthreads();
        sh[t] += add;
        __syncthreads();
    }
    if (t < NB) boff[t] = sh[t] - v;
}

__global__ void k_rowptr(const int* __restrict__ deg, const int* __restrict__ boff,
                         int* __restrict__ rowptr, int* __restrict__ cursor) {
    __shared__ int sh[128];
    int i = blockIdx.x * 128 + threadIdx.x;
    int t = threadIdx.x;
    int v = (i < NN) ? deg[i] : 0;
    sh[t] = v;
    __syncthreads();
    for (int s = 1; s < 128; s <<= 1) {
        int add = (t >= s) ? sh[t - s] : 0;
        __syncthreads();
        sh[t] += add;
        __syncthreads();
    }
    if (i < NN) {
        int off = boff[blockIdx.x] + sh[t] - v;
        rowptr[i] = off;
        cursor[i] = off;
    }
    if (blockIdx.x == 0 && t == 0) rowptr[NN] = EE;
}

__global__ void k_scatter(const int* __restrict__ src, const int* __restrict__ dst,
                          int* __restrict__ cursor, int* __restrict__ nbr) {
    int e = blockIdx.x * blockDim.x + threadIdx.x;
    if (e >= EE) return;
    int d = dst[e];
    if ((unsigned)d >= NN) return;
    int p = atomicAdd(&cursor[d], 1);
    nbr[p] = src[e];
}

// ============================================================================
// aggregation: agg[r] = hin[r] + sum_{s in nbr(r)} hin[s]   (warp per row)
// ============================================================================
__global__ void __launch_bounds__(256) agg_kernel(
    const float* __restrict__ hin, float* __restrict__ agg,
    const int* __restrict__ rowptr, const int* __restrict__ nbr) {
    int warp = (blockIdx.x * 256 + threadIdx.x) >> 5;
    int lane = threadIdx.x & 31;
    if (warp >= NN) return;
    size_t rb = (size_t)warp * FF;
    float a0 = hin[rb + lane];
    float a1 = hin[rb + lane + 32];
    int beg = rowptr[warp], end = rowptr[warp + 1];
    for (int j = beg; j < end; j++) {
        int s = __ldg(&nbr[j]);
        size_t sb = (size_t)s * FF;
        a0 += hin[sb + lane];
        a1 += hin[sb + lane + 32];
    }
    agg[rb + lane] = a0;
    agg[rb + lane + 32] = a1;
}

// ============================================================================
// wmma tf32 MLP: hout = sig(sig(agg @ W1) @ W2), 3xTF32 split for accuracy
// block = 256 threads (8 warps), tile = 128 rows x 64 cols
// ============================================================================
__device__ __forceinline__ float fast_sigmoid(float x) {
    return __fdividef(1.0f, 1.0f + __expf(-x));
}
__device__ __forceinline__ float tf32_hi(float a) {
    return __uint_as_float(__float_as_uint(a) & 0xFFFFE000u);
}

// smem (floats): Ahi[128*LDA] Alo[128*LDA] W1hi[64*LDA] W1lo[64*LDA] W2hi[64*LDA] W2lo[64*LDA]
// Ctmp (128*LDA) aliases [W1hi,W1lo]. SAFE only because gemm_3xtf32 has a
// __syncthreads() between all fragment loads and the accumulator stores.
#define SMEM_FLOATS (128 * LDA * 2 + 64 * LDA * 4)
#define SMEM_BYTES (SMEM_FLOATS * 4)

__device__ __forceinline__ void gemm_3xtf32(
    const float* __restrict__ Ahi, const float* __restrict__ Alo,
    const float* __restrict__ Whi, const float* __restrict__ Wlo,
    float* __restrict__ Ctmp, int warp) {
    wmma::fragment<wmma::accumulator, 16, 16, 8, float> acc[4];
#pragma unroll
    for (int nt = 0; nt < 4; nt++) wmma::fill_fragment(acc[nt], 0.0f);
    const float* arow_hi = Ahi + (warp * 16) * LDA;
    const float* arow_lo = Alo + (warp * 16) * LDA;
#pragma unroll
    for (int k = 0; k < 64; k += 8) {
        wmma::fragment<wmma::matrix_a, 16, 16, 8, wmma::precision::tf32, wmma::row_major> aHi, aLo;
        wmma::load_matrix_sync(aHi, arow_hi + k, LDA);
        wmma::load_matrix_sync(aLo, arow_lo + k, LDA);
#pragma unroll
        for (int nt = 0; nt < 4; nt++) {
            // W stored transposed [n][k] with ld=LDA -> col_major (k,n) at n*LDA+k
            wmma::fragment<wmma::matrix_b, 16, 16, 8, wmma::precision::tf32, wmma::col_major> bHi, bLo;
            wmma::load_matrix_sync(bHi, Whi + (nt * 16) * LDA + k, LDA);
            wmma::load_matrix_sync(bLo, Wlo + (nt * 16) * LDA + k, LDA);
            wmma::mma_sync(acc[nt], aHi, bHi, acc[nt]);
            wmma::mma_sync(acc[nt], aHi, bLo, acc[nt]);
            wmma::mma_sync(acc[nt], aLo, bHi, acc[nt]);
        }
    }
    // CRITICAL: Ctmp aliases the W operand region. Every warp must finish ALL
    // its W-fragment loads before ANY warp stores its accumulator tile.
    __syncthreads();
#pragma unroll
    for (int nt = 0; nt < 4; nt++)
        wmma::store_matrix_sync(Ctmp + (warp * 16) * LDA + nt * 16, acc[nt], LDA, wmma::mem_row_major);
}

__global__ void __launch_bounds__(256) mlp_wmma_kernel(
    const float* __restrict__ agg, float* __restrict__ hout,
    const float* __restrict__ W1, const float* __restrict__ W2) {
    extern __shared__ float sm[];
    float* Ahi = sm;
    float* Alo = Ahi + 128 * LDA;
    float* W1hi = Alo + 128 * LDA;
    float* W1lo = W1hi + 64 * LDA;
    float* W2hi = W1lo + 64 * LDA;
    float* W2lo = W2hi + 64 * LDA;
    float* Ctmp = W1hi;  // 128*LDA, reused; see barrier in gemm_3xtf32

    int tid = threadIdx.x;
    int warp = tid >> 5;
    int row0 = blockIdx.x * 128;

    // stage weights transposed + split: Wt[n][k] = W[k][n]
    for (int i = tid; i < FF * FF; i += 256) {
        int k = i >> 6, n = i & 63;
        float w1 = W1[i], w2 = W2[i];
        float w1h = tf32_hi(w1), w2h = tf32_hi(w2);
        W1hi[n * LDA + k] = w1h;
        W1lo[n * LDA + k] = w1 - w1h;
        W2hi[n * LDA + k] = w2h;
        W2lo[n * LDA + k] = w2 - w2h;
    }
    // stage A rows + split
    for (int i = tid; i < 128 * FF; i += 256) {
        int r = i >> 6, c = i & 63;
        float v = (row0 + r < NN) ? agg[(size_t)(row0 + r) * FF + c] : 0.f;
        float vh = tf32_hi(v);
        Ahi[r * LDA + c] = vh;
        Alo[r * LDA + c] = v - vh;
    }
    __syncthreads();

    // GEMM 1: Ctmp = A @ W1 (3xTF32); internal barrier protects Ctmp/W1 alias
    gemm_3xtf32(Ahi, Alo, W1hi, W1lo, Ctmp, warp);
    __syncthreads();

    // epilogue 1: sigmoid, restage into A (hi/lo)
    for (int i = tid; i < 128 * FF; i += 256) {
        int r = i >> 6, c = i & 63;
        float y = fast_sigmoid(Ctmp[r * LDA + c]);
        float yh = tf32_hi(y);
        Ahi[r * LDA + c] = yh;
        Alo[r * LDA + c] = y - yh;
    }
    __syncthreads();

    // GEMM 2: Ctmp = Y @ W2
    gemm_3xtf32(Ahi, Alo, W2hi, W2lo, Ctmp, warp);
    __syncthreads();

    // epilogue 2: sigmoid -> gmem (16 threads per row, float4)
    {
        int rl = tid >> 4;             // 0..15
        int c4 = (tid & 15) * 4;       // 0..60
#pragma unroll
        for (int rr = 0; rr < 128; rr += 16) {
            int r = row0 + rr + rl;
            if (r < NN) {
                const float* cs = Ctmp + (rr + rl) * LDA + c4;
                float4 v;
                v.x = fast_sigmoid(cs[0]);
                v.y = fast_sigmoid(cs[1]);
                v.z = fast_sigmoid(cs[2]);
                v.w = fast_sigmoid(cs[3]);
                *(float4*)(hout + (size_t)r * FF + c4) = v;
            }
        }
    }
}

// ============================================================================
// pool + head
// ============================================================================
__global__ void pool_kernel(const float* __restrict__ h,
                            const int* __restrict__ batch,
                            float* __restrict__ xr) {
    int t = blockIdx.x * blockDim.x + threadIdx.x;
    if (t < NN * FF) {
        int i = t >> 6;
        int f = t & 63;
        int b = batch[i];
        if ((unsigned)b < BB) atomicAdd(&xr[b * FF + f], h[t]);
    }
}

__global__ void head_kernel(const float* __restrict__ xr, const float* __restrict__ fcw,
                            const float* __restrict__ fcb, float* __restrict__ out) {
    __shared__ float w[CC * FF];
    __shared__ float b[CC];
    for (int i = threadIdx.x; i < CC * FF; i += blockDim.x) w[i] = fcw[i];
    if (threadIdx.x < CC) b[threadIdx.x] = fcb[threadIdx.x];
    __syncthreads();
    int r = threadIdx.x;
    if (r < BB) {
        float lg[CC];
        float m = -1e30f;
        const float* row = xr + r * FF;
#pragma unroll
        for (int j = 0; j < CC; j++) {
            float a = b[j];
#pragma unroll
            for (int k = 0; k < FF; k++) a = fmaf(row[k], w[j * FF + k], a);
            lg[j] = a;
            m = fmaxf(m, a);
        }
        float s = 0.f;
#pragma unroll
        for (int j = 0; j < CC; j++) s += expf(lg[j] - m);
        float lse = m + logf(s);
#pragma unroll
        for (int j = 0; j < CC; j++) out[r * CC + j] = lg[j] - lse;
    }
}

// ============================================================================
extern "C" void kernel_launch(void* const* d_in, const int* in_sizes, int n_in,
                              void* d_out, int out_size) {
    const float* x = (const float*)d_in[0];
    const void* ei = d_in[1];
    const void* batch = d_in[2];
    const float* W1s = (const float*)d_in[3];
    const float* W2s = (const float*)d_in[4];
    const float* fcw = (const float*)d_in[5];
    const float* fcb = (const float*)d_in[6];
    float* out = (float*)d_out;

    float *hA, *hB;
    int *src, *dst, *nbr, *deg, *rowptr, *cursor, *bt, *bsum, *boff, *flags;
    cudaGetSymbolAddress((void**)&hA, d_hA);
    cudaGetSymbolAddress((void**)&hB, d_hB);
    cudaGetSymbolAddress((void**)&src, d_src);
    cudaGetSymbolAddress((void**)&dst, d_dst);
    cudaGetSymbolAddress((void**)&nbr, d_nbr);
    cudaGetSymbolAddress((void**)&deg, d_deg);
    cudaGetSymbolAddress((void**)&rowptr, d_rowptr);
    cudaGetSymbolAddress((void**)&cursor, d_cursor);
    cudaGetSymbolAddress((void**)&bt, d_batch);
    cudaGetSymbolAddress((void**)&bsum, d_bsum);
    cudaGetSymbolAddress((void**)&boff, d_boff);
    cudaGetSymbolAddress((void**)&flags, d_flags);

    cudaFuncSetAttribute(mlp_wmma_kernel, cudaFuncAttributeMaxDynamicSharedMemorySize, SMEM_BYTES);

    // preprocessing
    cudaMemsetAsync(deg, 0, NN * sizeof(int));
    detect_kernel<<<1, 256>>>((const unsigned*)ei, (const unsigned*)batch, flags);
    cvt_edges<<<(EE + 255) / 256, 256>>>(ei, src, dst, deg, flags);
    cvt_batch<<<(NN + 255) / 256, 256>>>(batch, bt, flags);
    k_bsum<<<NB, 128>>>(deg, bsum);
    k_bscan<<<1, 1024>>>(bsum, boff);
    k_rowptr<<<NB, 128>>>(deg, boff, rowptr, cursor);
    k_scatter<<<(EE + 255) / 256, 256>>>(src, dst, cursor, nbr);

    cudaMemsetAsync(d_out, 0, (size_t)out_size * sizeof(float));

    // 4 layers: gather -> wmma MLP
    const int agrid = (NN * 32 + 255) / 256;   // warp per node
    const float* hin = x;
    for (int l = 0; l < LL; l++) {
        agg_kernel<<<agrid, 256>>>(hin, hA, rowptr, nbr);
        mlp_wmma_kernel<<<NTILE, 256, SMEM_BYTES>>>(hA, hB, W1s + l * FF * FF, W2s + l * FF * FF);
        hin = hB;
    }

    pool_kernel<<<(NN * FF + 255) / 256, 256>>>(hB, bt, out + BB * CC);
    head_kernel<<<1, 128>>>(out + BB * CC, fcw, fcb, out);
}

// round 7
// speedup vs baseline: 3.6095x; 1.7357x over previous
#include <cuda_runtime.h>
#include <cuda_bf16.h>
#include <mma.h>
#include <cstdint>

using namespace nvcuda;

#define NN 100000
#define EE 1600000
#define FF 64
#define CC 10
#define LL 4
#define BB 128
#define NB 782                      // ceil(NN/128)
#define NTILE 782                   // row tiles of 128 for the MLP GEMM
#define LDH 72                      // bf16 smem leading dim (elements)
#define LDC 72                      // fp32 C leading dim

// ---- scratch (__device__ globals; no allocs allowed) ----------------------
__device__ float d_hA[(size_t)NN * FF];   // agg scratch
__device__ float d_hB[(size_t)NN * FF];   // h ping buffer
__device__ int d_src[EE];
__device__ int d_dst[EE];
__device__ int d_nbr[EE];
__device__ int d_deg[NN];
__device__ int d_rowptr[NN + 1];
__device__ int d_cursor[NN];
__device__ int d_batch[NN];
__device__ int d_bsum[1024];
__device__ int d_boff[1024];
__device__ int d_flags[2];

// ============================================================================
// preprocessing (dtype detect, int32 convert, CSR build)
// ============================================================================
__global__ void detect_kernel(const unsigned* __restrict__ ei,
                              const unsigned* __restrict__ bt,
                              int* __restrict__ flags) {
    if (threadIdx.x == 0) { flags[0] = 0; flags[1] = 0; }
    __syncthreads();
    int t = threadIdx.x;
    unsigned a = ei[2 * (t * 6000) + 1];
    if (a != 0u) atomicOr(&flags[0], 1);
    int i = NN / 4 + t * 97;
    unsigned b = bt[2 * i + 1];
    if (b != 0u) atomicOr(&flags[1], 1);
}

__global__ void cvt_edges(const void* __restrict__ ei,
                          int* __restrict__ src, int* __restrict__ dst,
                          int* __restrict__ deg, const int* __restrict__ flags) {
    int e = blockIdx.x * blockDim.x + threadIdx.x;
    if (e >= EE) return;
    int s, d;
    if (flags[0]) {
        s = ((const int*)ei)[e];
        d = ((const int*)ei)[EE + e];
    } else {
        s = (int)((const long long*)ei)[e];
        d = (int)((const long long*)ei)[EE + e];
    }
    src[e] = s;
    dst[e] = d;
    if ((unsigned)d < NN) atomicAdd(&deg[d], 1);
}

__global__ void cvt_batch(const void* __restrict__ bt,
                          int* __restrict__ out, const int* __restrict__ flags) {
    int i = blockIdx.x * blockDim.x + threadIdx.x;
    if (i >= NN) return;
    out[i] = flags[1] ? ((const int*)bt)[i] : (int)((const long long*)bt)[i];
}

__global__ void k_bsum(const int* __restrict__ deg, int* __restrict__ bsum) {
    __shared__ int sh[128];
    int i = blockIdx.x * 128 + threadIdx.x;
    int v = (i < NN) ? deg[i] : 0;
    sh[threadIdx.x] = v;
    __syncthreads();
    for (int s = 64; s > 0; s >>= 1) {
        if (threadIdx.x < s) sh[threadIdx.x] += sh[threadIdx.x + s];
        __syncthreads();
    }
    if (threadIdx.x == 0) bsum[blockIdx.x] = sh[0];
}

__global__ void k_bscan(const int* __restrict__ bsum, int* __restrict__ boff) {
    __shared__ int sh[1024];
    int t = threadIdx.x;
    int v = (t < NB) ? bsum[t] : 0;
    sh[t] = v;
    __syncthreads();
    for (int s = 1; s < 1024; s <<= 1) {
        int add = (t >= s) ? sh[t - s] : 0;
        __syncthreads();
        sh[t] += add;
        __syncthreads();
    }
    if (t < NB) boff[t] = sh[t] - v;
}

__global__ void k_rowptr(const int* __restrict__ deg, const int* __restrict__ boff,
                         int* __restrict__ rowptr, int* __restrict__ cursor) {
    __shared__ int sh[128];
    int i = blockIdx.x * 128 + threadIdx.x;
    int t = threadIdx.x;
    int v = (i < NN) ? deg[i] : 0;
    sh[t] = v;
    __syncthreads();
    for (int s = 1; s < 128; s <<= 1) {
        int add = (t >= s) ? sh[t - s] : 0;
        __syncthreads();
        sh[t] += add;
        __syncthreads();
    }
    if (i < NN) {
        int off = boff[blockIdx.x] + sh[t] - v;
        rowptr[i] = off;
        cursor[i] = off;
    }
    if (blockIdx.x == 0 && t == 0) rowptr[NN] = EE;
}

__global__ void k_scatter(const int* __restrict__ src, const int* __restrict__ dst,
                          int* __restrict__ cursor, int* __restrict__ nbr) {
    int e = blockIdx.x * blockDim.x + threadIdx.x;
    if (e >= EE) return;
    int d = dst[e];
    if ((unsigned)d >= NN) return;
    int p = atomicAdd(&cursor[d], 1);
    nbr[p] = src[e];
}

// ============================================================================
// aggregation: agg[r] = hin[r] + sum_{s in nbr(r)} hin[s]   (warp per row)
// ============================================================================
__global__ void __launch_bounds__(256) agg_kernel(
    const float* __restrict__ hin, float* __restrict__ agg,
    const int* __restrict__ rowptr, const int* __restrict__ nbr) {
    int warp = (blockIdx.x * 256 + threadIdx.x) >> 5;
    int lane = threadIdx.x & 31;
    if (warp >= NN) return;
    size_t rb = (size_t)warp * FF;
    float a0 = hin[rb + lane];
    float a1 = hin[rb + lane + 32];
    int beg = rowptr[warp], end = rowptr[warp + 1];
    for (int j = beg; j < end; j++) {
        int s = __ldg(&nbr[j]);
        size_t sb = (size_t)s * FF;
        a0 += hin[sb + lane];
        a1 += hin[sb + lane + 32];
    }
    agg[rb + lane] = a0;
    agg[rb + lane + 32] = a1;
}

// ============================================================================
// wmma bf16 MLP: hout = sig(sig(agg @ W1) @ W2), 3xBF16 split for accuracy
// block = 256 threads (8 warps), tile = 128 rows x 64 cols, 108KB smem
// ============================================================================
__device__ __forceinline__ float fast_sigmoid(float x) {
    return __fdividef(1.0f, 1.0f + __expf(-x));
}
__device__ __forceinline__ void bf16_split(float v, __nv_bfloat16& hi, __nv_bfloat16& lo) {
    hi = __float2bfloat16_rn(v);
    lo = __float2bfloat16_rn(v - __bfloat162float(hi));
}

// smem layout (bytes from base):
//  Ahi  : 128*LDH*2 = 18432     Alo : 18432
//  W1hi : 64*LDH*2 = 9216       W1lo: 9216   W2hi: 9216   W2lo: 9216
//  C    : 128*LDC*4 = 36864
#define SM_AHI  0
#define SM_ALO  18432
#define SM_W1HI 36864
#define SM_W1LO 46080
#define SM_W2HI 55296
#define SM_W2LO 64512
#define SM_C    73728
#define SMEM_BYTES (73728 + 36864)   // 110592 = 108KB -> 2 blocks/SM

__device__ __forceinline__ void gemm_3xbf16(
    const __nv_bfloat16* Ahi, const __nv_bfloat16* Alo,
    const __nv_bfloat16* Whi, const __nv_bfloat16* Wlo,
    float* C, int warp) {
    wmma::fragment<wmma::accumulator, 16, 16, 16, float> acc[4];
#pragma unroll
    for (int nt = 0; nt < 4; nt++) wmma::fill_fragment(acc[nt], 0.0f);
    const __nv_bfloat16* arow_hi = Ahi + (warp * 16) * LDH;
    const __nv_bfloat16* arow_lo = Alo + (warp * 16) * LDH;
#pragma unroll
    for (int k = 0; k < 64; k += 16) {
        wmma::fragment<wmma::matrix_a, 16, 16, 16, __nv_bfloat16, wmma::row_major> aHi, aLo;
        wmma::load_matrix_sync(aHi, arow_hi + k, LDH);
        wmma::load_matrix_sync(aLo, arow_lo + k, LDH);
#pragma unroll
        for (int nt = 0; nt < 4; nt++) {
            // W stored transposed [n][k] -> col_major (k,n) at n*LDH+k
            wmma::fragment<wmma::matrix_b, 16, 16, 16, __nv_bfloat16, wmma::col_major> bHi, bLo;
            wmma::load_matrix_sync(bHi, Whi + (nt * 16) * LDH + k, LDH);
            wmma::load_matrix_sync(bLo, Wlo + (nt * 16) * LDH + k, LDH);
            wmma::mma_sync(acc[nt], aHi, bHi, acc[nt]);
            wmma::mma_sync(acc[nt], aHi, bLo, acc[nt]);
            wmma::mma_sync(acc[nt], aLo, bHi, acc[nt]);
        }
    }
#pragma unroll
    for (int nt = 0; nt < 4; nt++)
        wmma::store_matrix_sync(C + (warp * 16) * LDC + nt * 16, acc[nt], LDC, wmma::mem_row_major);
}

__global__ void __launch_bounds__(256) mlp_wmma_kernel(
    const float* __restrict__ agg, float* __restrict__ hout,
    const float* __restrict__ W1, const float* __restrict__ W2) {
    extern __shared__ char smb[];
    __nv_bfloat16* Ahi = (__nv_bfloat16*)(smb + SM_AHI);
    __nv_bfloat16* Alo = (__nv_bfloat16*)(smb + SM_ALO);
    __nv_bfloat16* W1hi = (__nv_bfloat16*)(smb + SM_W1HI);
    __nv_bfloat16* W1lo = (__nv_bfloat16*)(smb + SM_W1LO);
    __nv_bfloat16* W2hi = (__nv_bfloat16*)(smb + SM_W2HI);
    __nv_bfloat16* W2lo = (__nv_bfloat16*)(smb + SM_W2LO);
    float* C = (float*)(smb + SM_C);

    int tid = threadIdx.x;
    int warp = tid >> 5;
    int row0 = blockIdx.x * 128;

    // stage weights transposed + split: Wt[n][k] = W[k][n]
    for (int i = tid; i < FF * FF; i += 256) {
        int k = i >> 6, n = i & 63;
        __nv_bfloat16 h1, l1, h2, l2;
        bf16_split(W1[i], h1, l1);
        bf16_split(W2[i], h2, l2);
        W1hi[n * LDH + k] = h1;
        W1lo[n * LDH + k] = l1;
        W2hi[n * LDH + k] = h2;
        W2lo[n * LDH + k] = l2;
    }
    // stage A rows + split (float2 reads, bf162 writes)
    for (int i = tid; i < 128 * 32; i += 256) {
        int r = i >> 5, c2 = (i & 31) * 2;
        float2 v = make_float2(0.f, 0.f);
        if (row0 + r < NN) v = *(const float2*)(agg + (size_t)(row0 + r) * FF + c2);
        __nv_bfloat16 hx, lx, hy, ly;
        bf16_split(v.x, hx, lx);
        bf16_split(v.y, hy, ly);
        *(__nv_bfloat162*)(Ahi + r * LDH + c2) = __nv_bfloat162(hx, hy);
        *(__nv_bfloat162*)(Alo + r * LDH + c2) = __nv_bfloat162(lx, ly);
    }
    __syncthreads();

    // GEMM 1: C = A @ W1 (3xBF16)
    gemm_3xbf16(Ahi, Alo, W1hi, W1lo, C, warp);
    __syncthreads();

    // epilogue 1: sigmoid, restage into A (hi/lo)
    for (int i = tid; i < 128 * 32; i += 256) {
        int r = i >> 5, c2 = (i & 31) * 2;
        const float* cs = C + r * LDC + c2;
        float yx = fast_sigmoid(cs[0]);
        float yy = fast_sigmoid(cs[1]);
        __nv_bfloat16 hx, lx, hy, ly;
        bf16_split(yx, hx, lx);
        bf16_split(yy, hy, ly);
        *(__nv_bfloat162*)(Ahi + r * LDH + c2) = __nv_bfloat162(hx, hy);
        *(__nv_bfloat162*)(Alo + r * LDH + c2) = __nv_bfloat162(lx, ly);
    }
    __syncthreads();

    // GEMM 2: C = Y @ W2
    gemm_3xbf16(Ahi, Alo, W2hi, W2lo, C, warp);
    __syncthreads();

    // epilogue 2: sigmoid -> gmem (16 threads per row, float4)
    {
        int rl = tid >> 4;             // 0..15
        int c4 = (tid & 15) * 4;       // 0..60
#pragma unroll
        for (int rr = 0; rr < 128; rr += 16) {
            int r = row0 + rr + rl;
            if (r < NN) {
                const float* cs = C + (rr + rl) * LDC + c4;
                float4 v;
                v.x = fast_sigmoid(cs[0]);
                v.y = fast_sigmoid(cs[1]);
                v.z = fast_sigmoid(cs[2]);
                v.w = fast_sigmoid(cs[3]);
                *(float4*)(hout + (size_t)r * FF + c4) = v;
            }
        }
    }
}

// ============================================================================
// pool: sorted-batch smem binning; global atomics only per (graph,feat) bin
// ============================================================================
__global__ void __launch_bounds__(256) pool_kernel(
    const float* __restrict__ h, const int* __restrict__ batch,
    float* __restrict__ xr) {
    __shared__ float acc[8][64];
    __shared__ int g0s;
    int t = threadIdx.x;
    int n0 = blockIdx.x * 256;
    for (int i = t; i < 512; i += 256) ((float*)acc)[i] = 0.f;
    if (t == 0) g0s = batch[n0];
    __syncthreads();
    int g0 = g0s;
    int f = t & 63, nl = t >> 6;   // 4 node lanes x 64 feats
#pragma unroll 4
    for (int k = 0; k < 64; k++) {
        int i = n0 + nl * 64 + k;
        if (i < NN) {
            int g = batch[i] - g0;
            float v = h[(size_t)i * FF + f];
            if ((unsigned)g < 8u) {
                atomicAdd(&acc[g][f], v);
            } else {
                int b = batch[i];
                if ((unsigned)b < BB) atomicAdd(&xr[b * FF + f], v);
            }
        }
    }
    __syncthreads();
    for (int gi = nl; gi < 8; gi += 4) {
        float v = acc[gi][f];
        int b = g0 + gi;
        if (v != 0.f && (unsigned)b < BB) atomicAdd(&xr[b * FF + f], v);
    }
}

// ============================================================================
// head: logits = xr @ fc_w^T + fc_b; out = log_softmax(logits)
// ============================================================================
__global__ void head_kernel(const float* __restrict__ xr, const float* __restrict__ fcw,
                            const float* __restrict__ fcb, float* __restrict__ out) {
    __shared__ float w[CC * FF];
    __shared__ float b[CC];
    for (int i = threadIdx.x; i < CC * FF; i += blockDim.x) w[i] = fcw[i];
    if (threadIdx.x < CC) b[threadIdx.x] = fcb[threadIdx.x];
    __syncthreads();
    int r = threadIdx.x;
    if (r < BB) {
        float lg[CC];
        float m = -1e30f;
        const float* row = xr + r * FF;
#pragma unroll
        for (int j = 0; j < CC; j++) {
            float a = b[j];
#pragma unroll
            for (int k = 0; k < FF; k++) a = fmaf(row[k], w[j * FF + k], a);
            lg[j] = a;
            m = fmaxf(m, a);
        }
        float s = 0.f;
#pragma unroll
        for (int j = 0; j < CC; j++) s += expf(lg[j] - m);
        float lse = m + logf(s);
#pragma unroll
        for (int j = 0; j < CC; j++) out[r * CC + j] = lg[j] - lse;
    }
}

// ============================================================================
extern "C" void kernel_launch(void* const* d_in, const int* in_sizes, int n_in,
                              void* d_out, int out_size) {
    const float* x = (const float*)d_in[0];
    const void* ei = d_in[1];
    const void* batch = d_in[2];
    const float* W1s = (const float*)d_in[3];
    const float* W2s = (const float*)d_in[4];
    const float* fcw = (const float*)d_in[5];
    const float* fcb = (const float*)d_in[6];
    float* out = (float*)d_out;

    float *hA, *hB;
    int *src, *dst, *nbr, *deg, *rowptr, *cursor, *bt, *bsum, *boff, *flags;
    cudaGetSymbolAddress((void**)&hA, d_hA);
    cudaGetSymbolAddress((void**)&hB, d_hB);
    cudaGetSymbolAddress((void**)&src, d_src);
    cudaGetSymbolAddress((void**)&dst, d_dst);
    cudaGetSymbolAddress((void**)&nbr, d_nbr);
    cudaGetSymbolAddress((void**)&deg, d_deg);
    cudaGetSymbolAddress((void**)&rowptr, d_rowptr);
    cudaGetSymbolAddress((void**)&cursor, d_cursor);
    cudaGetSymbolAddress((void**)&bt, d_batch);
    cudaGetSymbolAddress((void**)&bsum, d_bsum);
    cudaGetSymbolAddress((void**)&boff, d_boff);
    cudaGetSymbolAddress((void**)&flags, d_flags);

    cudaFuncSetAttribute(mlp_wmma_kernel, cudaFuncAttributeMaxDynamicSharedMemorySize, SMEM_BYTES);

    // preprocessing
    cudaMemsetAsync(deg, 0, NN * sizeof(int));
    detect_kernel<<<1, 256>>>((const unsigned*)ei, (const unsigned*)batch, flags);
    cvt_edges<<<(EE + 255) / 256, 256>>>(ei, src, dst, deg, flags);
    cvt_batch<<<(NN + 255) / 256, 256>>>(batch, bt, flags);
    k_bsum<<<NB, 128>>>(deg, bsum);
    k_bscan<<<1, 1024>>>(bsum, boff);
    k_rowptr<<<NB, 128>>>(deg, boff, rowptr, cursor);
    k_scatter<<<(EE + 255) / 256, 256>>>(src, dst, cursor, nbr);

    cudaMemsetAsync(d_out, 0, (size_t)out_size * sizeof(float));

    // 4 layers: gather -> wmma MLP
    const int agrid = (NN * 32 + 255) / 256;   // warp per node
    const float* hin = x;
    for (int l = 0; l < LL; l++) {
        agg_kernel<<<agrid, 256>>>(hin, hA, rowptr, nbr);
        mlp_wmma_kernel<<<NTILE, 256, SMEM_BYTES>>>(hA, hB, W1s + l * FF * FF, W2s + l * FF * FF);
        hin = hB;
    }

    pool_kernel<<<(NN + 255) / 256, 256>>>(hB, bt, out + BB * CC);
    head_kernel<<<1, 128>>>(out + BB * CC, fcw, fcb, out);
}